// round 5
// baseline (speedup 1.0000x reference)
#include <cuda_runtime.h>
#include <math.h>

#define T_DIM 512
#define B_DIM 1024
#define K_DIM 48
#define START_TAG 46
#define STOP_TAG 47
#define FULLMASK 0xffffffffu
#define QD 4
#define WPB 2
#define THREADS (WPB * 32)

__device__ float g_c;   // per-step log-scale constant

// ---------- pre-kernel: zero out, compute scale constant c ----------
__global__ void crf_pre(const float* __restrict__ trans, float* __restrict__ out) {
    float s = 0.f;
    for (int i = threadIdx.x; i < K_DIM * K_DIM; i += 256) s += __expf(trans[i]);
#pragma unroll
    for (int off = 16; off; off >>= 1) s += __shfl_xor_sync(FULLMASK, s, off);
    __shared__ float red[8];
    if ((threadIdx.x & 31) == 0) red[threadIdx.x >> 5] = s;
    __syncthreads();
    if (threadIdx.x == 0) {
        float tot = 0.f;
#pragma unroll
        for (int i = 0; i < 8; i++) tot += red[i];
        g_c = __logf(tot / 46.0f);
        out[0] = 0.0f;
    }
}

__global__ __launch_bounds__(THREADS) void crf_fwd(
    const float* __restrict__ feats,      // (T, B, K)
    const float* __restrict__ trans,      // (K, K)  [next, prev]
    const int*   __restrict__ tags,       // (B, T)
    const int*   __restrict__ lengths,    // (B,)
    float* __restrict__ out)
{
    __shared__ float trans_sh[K_DIM * K_DIM];
    __shared__ __align__(16) float p_sh[WPB][2][K_DIM];   // double-buffered p vectors

    const int tid = threadIdx.x;
    const int warp = tid >> 5;
    const int lane = tid & 31;
    const int b = blockIdx.x * WPB + warp;
    const int j0 = lane;
    const int j1 = lane + 32;
    const bool has1 = (lane < 16);

    for (int i = tid; i < K_DIM * K_DIM; i += THREADS) trans_sh[i] = trans[i];
    __syncthreads();

    const float c = g_c;
    const float ec = __expf(-c);

    // scaled linear transition rows in scalar registers (R4-proven layout)
    float E0[K_DIM], E1[K_DIM];
#pragma unroll
    for (int i = 0; i < K_DIM; i++) {
        E0[i] = __expf(trans_sh[j0 * K_DIM + i]) * ec;
        E1[i] = has1 ? __expf(trans_sh[j1 * K_DIM + i]) * ec : 0.0f;
    }

    const int len = lengths[b];                 // in [1, T]
    const int stride = B_DIM * K_DIM;
    const float* fb = feats + b * K_DIM;
    const int* tagb = tags + b * T_DIM;

    // ---- t = 0: p_j = exp(feat0_j + trans[j][START]) ----
    float p0 = __expf(fb[j0] + trans_sh[j0 * K_DIM + START_TAG]);
    float p1 = has1 ? __expf(fb[j1] + trans_sh[j1 * K_DIM + START_TAG]) : 0.0f;
    float Mlog = 0.f;

    const int t0tag = __ldg(&tagb[0]);
    float gold = trans_sh[t0tag * K_DIM + START_TAG] + fb[t0tag];

    // ---- depth-QD prefetch queue: exp(feat) precomputed off-chain; clamped addrs ----
    float ef0[QD], ef1[QD], em[QD], gt[QD];
    {
        int ptag = t0tag;
#pragma unroll
        for (int s = 0; s < QD; s++) {
            int tp = s + 1; tp = (tp < len) ? tp : (len - 1);
            const float* ft = fb + tp * stride;
            ef0[s] = __expf(ft[j0]);
            ef1[s] = has1 ? __expf(ft[j1]) : 0.0f;
            const int tg = __ldg(&tagb[tp]);
            em[s] = ft[tg];
            gt[s] = trans_sh[tg * K_DIM + ptag];
            ptag = tg;
        }
    }
    int ptag_pf = __ldg(&tagb[(QD < len) ? QD : (len - 1)]);

    // seed shared buffer for step 1 (slot 0 uses buffer 0)
    p_sh[warp][0][j0] = p0;
    if (has1) p_sh[warp][0][j1] = p1;
    __syncwarp();

    int t = 1;
    const int nquads = (len - 1) >> 2;
    const int rem = (len - 1) & 3;

    for (int q = 0; q < nquads; q++) {
#pragma unroll
        for (int s = 0; s < QD; s++) {
            // -------- consume slot s (step t): matvec in linear space --------
            const float* buf = p_sh[warp][s & 1];
            float s0a = 0.f, s0b = 0.f, s0c = 0.f, s0d = 0.f;
            float s1a = 0.f, s1b = 0.f, s1c = 0.f, s1d = 0.f;
            const float4* av = (const float4*)buf;
#pragma unroll
            for (int k = 0; k < K_DIM / 4; k++) {
                const float4 a = av[k];
                const int i = k * 4;
                s0a = fmaf(a.x, E0[i + 0], s0a);
                s0b = fmaf(a.y, E0[i + 1], s0b);
                s0c = fmaf(a.z, E0[i + 2], s0c);
                s0d = fmaf(a.w, E0[i + 3], s0d);
                s1a = fmaf(a.x, E1[i + 0], s1a);
                s1b = fmaf(a.y, E1[i + 1], s1b);
                s1c = fmaf(a.z, E1[i + 2], s1c);
                s1d = fmaf(a.w, E1[i + 3], s1d);
            }
            p0 = ef0[s] * ((s0a + s0b) + (s0c + s0d));
            p1 = ef1[s] * ((s1a + s1b) + (s1c + s1d));
            gold += gt[s] + em[s];

            // -------- refill slot s with step t+QD (clamped, branch-free) --------
            int tp = t + QD; tp = (tp < len) ? tp : (len - 1);
            const float* ft = fb + tp * stride;
            ef0[s] = __expf(ft[j0]);
            ef1[s] = has1 ? __expf(ft[j1]) : 0.0f;
            const int tg = __ldg(&tagb[tp]);
            em[s] = ft[tg];
            gt[s] = trans_sh[tg * K_DIM + ptag_pf];
            ptag_pf = tg;

            // -------- publish p for step t+1 --------
            float* wb = p_sh[warp][(s + 1) & 1];
            wb[j0] = p0;
            if (has1) wb[j1] = p1;
            __syncwarp();
            t++;
        }

        // renorm every 2 quads = 8 steps (uniform cheap branch, off steady chain)
        if (q & 1) {
            const float x = __shfl_sync(FULLMASK, p0, 0);   // p[tag0] > 0 always
            Mlog += __logf(x);
            const float r = __frcp_rn(x);
            p0 *= r;
            p1 *= r;
            float* wb = p_sh[warp][0];                      // next slot 0 reads buffer 0
            wb[j0] = p0;
            if (has1) wb[j1] = p1;
            __syncwarp();
        }
    }

    // -------- remainder (0..3 steps), static slot indices --------
#pragma unroll
    for (int s = 0; s < 3; s++) {
        if (s < rem) {
            const float* buf = p_sh[warp][s & 1];
            float s0a = 0.f, s0b = 0.f, s0c = 0.f, s0d = 0.f;
            float s1a = 0.f, s1b = 0.f, s1c = 0.f, s1d = 0.f;
            const float4* av = (const float4*)buf;
#pragma unroll
            for (int k = 0; k < K_DIM / 4; k++) {
                const float4 a = av[k];
                const int i = k * 4;
                s0a = fmaf(a.x, E0[i + 0], s0a);
                s0b = fmaf(a.y, E0[i + 1], s0b);
                s0c = fmaf(a.z, E0[i + 2], s0c);
                s0d = fmaf(a.w, E0[i + 3], s0d);
                s1a = fmaf(a.x, E1[i + 0], s1a);
                s1b = fmaf(a.y, E1[i + 1], s1b);
                s1c = fmaf(a.z, E1[i + 2], s1c);
                s1d = fmaf(a.w, E1[i + 3], s1d);
            }
            p0 = ef0[s] * ((s0a + s0b) + (s0c + s0d));
            p1 = ef1[s] * ((s1a + s1b) + (s1c + s1d));
            gold += gt[s] + em[s];

            float* wb = p_sh[warp][(s + 1) & 1];
            wb[j0] = p0;
            if (has1) wb[j1] = p1;
            __syncwarp();
        }
    }

    // ---- log_z = Mlog + c*(len-1) + log( sum_j p_j * exp(trans[STOP][j]) ) ----
    const float eS0 = __expf(trans_sh[STOP_TAG * K_DIM + j0]);
    const float eS1 = has1 ? __expf(trans_sh[STOP_TAG * K_DIM + j1]) : 0.0f;
    float v = fmaf(p0, eS0, p1 * eS1);
#pragma unroll
    for (int off = 16; off > 0; off >>= 1)
        v += __shfl_xor_sync(FULLMASK, v, off);

    const int lastTag = __ldg(&tagb[len - 1]);
    gold += trans_sh[STOP_TAG * K_DIM + lastTag];

    const float log_z = Mlog + c * (float)(len - 1) + __logf(v);

    if (lane == 0) atomicAdd(out, log_z - gold);
}

extern "C" void kernel_launch(void* const* d_in, const int* in_sizes, int n_in,
                              void* d_out, int out_size) {
    const float* feats   = (const float*)d_in[0];
    const float* trans   = (const float*)d_in[1];
    const int*   tags    = (const int*)d_in[2];
    const int*   lengths = (const int*)d_in[3];
    float* out = (float*)d_out;

    crf_pre<<<1, 256>>>(trans, out);
    crf_fwd<<<B_DIM / WPB, THREADS>>>(feats, trans, tags, lengths, out);
}

// round 6
// speedup vs baseline: 1.2257x; 1.2257x over previous
#include <cuda_runtime.h>
#include <math.h>

#define T_DIM 512
#define B_DIM 1024
#define K_DIM 48
#define START_TAG 46
#define STOP_TAG 47
#define NEG_VAL -10000.0f
#define FULLMASK 0xffffffffu
#define QD 4
#define WPB 4
#define THREADS (WPB * 32)
#define NBLOCKS 148

__device__ int g_next;
__device__ int g_order[B_DIM];

// ---------- pre-kernel: zero out, sort chains longest-first, reset cursor ----------
__global__ void crf_pre(const int* __restrict__ lengths, float* __restrict__ out) {
    __shared__ int cnt[T_DIM + 1];
    __shared__ int off[T_DIM + 1];
    const int tid = threadIdx.x;              // 1024 threads == B_DIM
    for (int i = tid; i <= T_DIM; i += B_DIM) cnt[i] = 0;
    __syncthreads();
    const int len = lengths[tid];
    atomicAdd(&cnt[len], 1);
    __syncthreads();
    if (tid == 0) {
        int run = 0;
        for (int l = T_DIM; l >= 1; l--) { off[l] = run; run += cnt[l]; }
        g_next = 0;
        out[0] = 0.0f;
    }
    __syncthreads();
    const int pos = atomicAdd(&off[len], 1);  // descending-length order
    g_order[pos] = tid;
}

// ---------- main: persistent warps, longest-first work stealing, R4 log-space body ----------
__global__ __launch_bounds__(THREADS) void crf_fwd(
    const float* __restrict__ feats,      // (T, B, K)
    const float* __restrict__ trans,      // (K, K)  [next, prev]
    const int*   __restrict__ tags,       // (B, T)
    const int*   __restrict__ lengths,    // (B,)
    float* __restrict__ out)
{
    __shared__ float trans_sh[K_DIM * K_DIM];
    __shared__ __align__(16) float a_sh[WPB][2][K_DIM];

    const int tid = threadIdx.x;
    const int warp = tid >> 5;
    const int lane = tid & 31;
    const int j0 = lane;
    const int j1 = lane + 32;
    const bool has1 = (lane < 16);

    for (int i = tid; i < K_DIM * K_DIM; i += THREADS) trans_sh[i] = trans[i];
    __syncthreads();

    // E rows in scalar registers, hoisted once per persistent warp
    float E0[K_DIM], E1[K_DIM];
#pragma unroll
    for (int i = 0; i < K_DIM; i++) {
        E0[i] = __expf(trans_sh[j0 * K_DIM + i]);
        E1[i] = has1 ? __expf(trans_sh[j1 * K_DIM + i]) : 0.0f;
    }

    const int stride = B_DIM * K_DIM;

    for (;;) {
        // -------- grab next chain (longest-first) --------
        int idx;
        if (lane == 0) idx = atomicAdd(&g_next, 1);
        idx = __shfl_sync(FULLMASK, idx, 0);
        if (idx >= B_DIM) break;
        const int b = g_order[idx];

        const int len = lengths[b];               // in [1, T]
        const float* fb = feats + b * K_DIM;
        const int* tagb = tags + b * T_DIM;

        // ---- t = 0 ----
        float alpha0 = fb[j0] + trans_sh[j0 * K_DIM + START_TAG];
        float alpha1 = has1 ? (fb[j1] + trans_sh[j1 * K_DIM + START_TAG]) : NEG_VAL;

        const int t0tag = __ldg(&tagb[0]);
        float gold = trans_sh[t0tag * K_DIM + START_TAG] + fb[t0tag];

        // ---- depth-QD prefetch queue (clamped addresses) ----
        float pf0[QD], pf1[QD], em[QD], gt[QD];
        {
            int ptag = t0tag;
#pragma unroll
            for (int s = 0; s < QD; s++) {
                int tp = s + 1; tp = (tp < len) ? tp : (len - 1);
                const float* ft = fb + tp * stride;
                pf0[s] = ft[j0];
                pf1[s] = has1 ? ft[j1] : 0.0f;
                const int tg = __ldg(&tagb[tp]);
                em[s] = ft[tg];
                gt[s] = trans_sh[tg * K_DIM + ptag];
                ptag = tg;
            }
        }
        int ptag_pf = __ldg(&tagb[(QD < len) ? QD : (len - 1)]);

        int t = 1;
        const int nquads = (len - 1) >> 2;
        const int rem = (len - 1) & 3;

        for (int q = 0; q < nquads; q++) {
#pragma unroll
            for (int s = 0; s < QD; s++) {
                // -------- consume slot s (step t) --------
                const float m = __shfl_sync(FULLMASK, alpha0, 0);
                const float a0 = __expf(alpha0 - m);
                const float a1 = __expf(alpha1 - m);

                float* buf = a_sh[warp][s & 1];
                buf[j0] = a0;
                if (has1) buf[j1] = a1;
                __syncwarp();

                float s0a = 0.f, s0b = 0.f, s0c = 0.f, s0d = 0.f;
                float s1a = 0.f, s1b = 0.f, s1c = 0.f, s1d = 0.f;
                const float4* av = (const float4*)buf;
#pragma unroll
                for (int k = 0; k < K_DIM / 4; k++) {
                    const float4 a = av[k];
                    const int i = k * 4;
                    s0a = fmaf(a.x, E0[i + 0], s0a);
                    s0b = fmaf(a.y, E0[i + 1], s0b);
                    s0c = fmaf(a.z, E0[i + 2], s0c);
                    s0d = fmaf(a.w, E0[i + 3], s0d);
                    s1a = fmaf(a.x, E1[i + 0], s1a);
                    s1b = fmaf(a.y, E1[i + 1], s1b);
                    s1c = fmaf(a.z, E1[i + 2], s1c);
                    s1d = fmaf(a.w, E1[i + 3], s1d);
                }
                alpha0 = pf0[s] + m + __logf((s0a + s0b) + (s0c + s0d));
                alpha1 = pf1[s] + m + __logf((s1a + s1b) + (s1c + s1d));
                gold += gt[s] + em[s];

                // -------- refill slot s with step t+QD (clamped) --------
                int tp = t + QD; tp = (tp < len) ? tp : (len - 1);
                const float* ft = fb + tp * stride;
                pf0[s] = ft[j0];
                pf1[s] = has1 ? ft[j1] : 0.0f;
                const int tg = __ldg(&tagb[tp]);
                em[s] = ft[tg];
                gt[s] = trans_sh[tg * K_DIM + ptag_pf];
                ptag_pf = tg;
                t++;
            }
        }

        // -------- remainder (0..3 steps) --------
#pragma unroll
        for (int s = 0; s < 3; s++) {
            if (s < rem) {
                const float m = __shfl_sync(FULLMASK, alpha0, 0);
                const float a0 = __expf(alpha0 - m);
                const float a1 = __expf(alpha1 - m);

                float* buf = a_sh[warp][s & 1];
                __syncwarp();
                buf[j0] = a0;
                if (has1) buf[j1] = a1;
                __syncwarp();

                float s0a = 0.f, s0b = 0.f, s0c = 0.f, s0d = 0.f;
                float s1a = 0.f, s1b = 0.f, s1c = 0.f, s1d = 0.f;
                const float4* av = (const float4*)buf;
#pragma unroll
                for (int k = 0; k < K_DIM / 4; k++) {
                    const float4 a = av[k];
                    const int i = k * 4;
                    s0a = fmaf(a.x, E0[i + 0], s0a);
                    s0b = fmaf(a.y, E0[i + 1], s0b);
                    s0c = fmaf(a.z, E0[i + 2], s0c);
                    s0d = fmaf(a.w, E0[i + 3], s0d);
                    s1a = fmaf(a.x, E1[i + 0], s1a);
                    s1b = fmaf(a.y, E1[i + 1], s1b);
                    s1c = fmaf(a.z, E1[i + 2], s1c);
                    s1d = fmaf(a.w, E1[i + 3], s1d);
                }
                alpha0 = pf0[s] + m + __logf((s0a + s0b) + (s0c + s0d));
                alpha1 = pf1[s] + m + __logf((s1a + s1b) + (s1c + s1d));
                gold += gt[s] + em[s];
            }
        }

        // ---- log_z = lse_j(alpha_j + trans[STOP, j]) ----
        float v0 = alpha0 + trans_sh[STOP_TAG * K_DIM + j0];
        float v1 = has1 ? (alpha1 + trans_sh[STOP_TAG * K_DIM + j1]) : -INFINITY;
        float mv = fmaxf(v0, v1);
#pragma unroll
        for (int off = 16; off > 0; off >>= 1)
            mv = fmaxf(mv, __shfl_xor_sync(FULLMASK, mv, off));
        float se = __expf(v0 - mv) + (has1 ? __expf(v1 - mv) : 0.0f);
#pragma unroll
        for (int off = 16; off > 0; off >>= 1)
            se += __shfl_xor_sync(FULLMASK, se, off);
        const float log_z = mv + __logf(se);

        const int lastTag = __ldg(&tagb[len - 1]);
        const float total = log_z - (gold + trans_sh[STOP_TAG * K_DIM + lastTag]);

        if (lane == 0) atomicAdd(out, total);
        __syncwarp();
    }
}

extern "C" void kernel_launch(void* const* d_in, const int* in_sizes, int n_in,
                              void* d_out, int out_size) {
    const float* feats   = (const float*)d_in[0];
    const float* trans   = (const float*)d_in[1];
    const int*   tags    = (const int*)d_in[2];
    const int*   lengths = (const int*)d_in[3];
    float* out = (float*)d_out;

    crf_pre<<<1, B_DIM>>>(lengths, out);
    crf_fwd<<<NBLOCKS, THREADS>>>(feats, trans, tags, lengths, out);
}

// round 7
// speedup vs baseline: 1.5034x; 1.2265x over previous
#include <cuda_runtime.h>
#include <math.h>

#define T_DIM 512
#define B_DIM 1024
#define K_DIM 48
#define START_TAG 46
#define STOP_TAG 47
#define NEG_VAL -10000.0f
#define FULLMASK 0xffffffffu
#define QD 4
#define WPB 8
#define THREADS (WPB * 32)
#define NBLOCKS 148

__device__ int g_order[B_DIM];

// ---------- pre-kernel: zero out, sort chains longest-first ----------
__global__ void crf_pre(const int* __restrict__ lengths, float* __restrict__ out) {
    __shared__ int cnt[T_DIM + 1];
    __shared__ int off[T_DIM + 1];
    const int tid = threadIdx.x;              // 1024 threads == B_DIM
    for (int i = tid; i <= T_DIM; i += B_DIM) cnt[i] = 0;
    __syncthreads();
    const int len = lengths[tid];
    atomicAdd(&cnt[len], 1);
    __syncthreads();
    if (tid == 0) {
        int run = 0;
        for (int l = T_DIM; l >= 1; l--) { off[l] = run; run += cnt[l]; }
        out[0] = 0.0f;
    }
    __syncthreads();
    const int pos = atomicAdd(&off[len], 1);  // descending-length order
    g_order[pos] = tid;
}

// ---------- main: 2 warps/SMSP, static interleaved LPT assignment ----------
__global__ __launch_bounds__(THREADS) void crf_fwd(
    const float* __restrict__ feats,      // (T, B, K)
    const float* __restrict__ trans,      // (K, K)  [next, prev]
    const int*   __restrict__ tags,       // (B, T)
    const int*   __restrict__ lengths,    // (B,)
    float* __restrict__ out)
{
    __shared__ float trans_sh[K_DIM * K_DIM];
    __shared__ __align__(16) float a_sh[WPB][2][K_DIM];

    const int tid = threadIdx.x;
    const int warp = tid >> 5;
    const int lane = tid & 31;
    const int j0 = lane;
    const int j1 = lane + 32;
    const bool has1 = (lane < 16);

    for (int i = tid; i < K_DIM * K_DIM; i += THREADS) trans_sh[i] = trans[i];
    __syncthreads();

    // stratified LPT assignment: rank = blockIdx.x + NBLOCKS*warp
    const int rank = blockIdx.x + NBLOCKS * warp;
    if (rank >= B_DIM) return;
    const int b = g_order[rank];

    // E rows in scalar registers
    float E0[K_DIM], E1[K_DIM];
#pragma unroll
    for (int i = 0; i < K_DIM; i++) {
        E0[i] = __expf(trans_sh[j0 * K_DIM + i]);
        E1[i] = has1 ? __expf(trans_sh[j1 * K_DIM + i]) : 0.0f;
    }

    const int len = lengths[b];               // in [1, T]
    const int stride = B_DIM * K_DIM;
    const float* fb = feats + b * K_DIM;
    const int* tagb = tags + b * T_DIM;

    // ---- t = 0 ----
    float alpha0 = fb[j0] + trans_sh[j0 * K_DIM + START_TAG];
    float alpha1 = has1 ? (fb[j1] + trans_sh[j1 * K_DIM + START_TAG]) : NEG_VAL;

    const int t0tag = __ldg(&tagb[0]);
    float gold = trans_sh[t0tag * K_DIM + START_TAG] + fb[t0tag];

    // lagged reference point (off critical chain): m for step t computed at step t-1
    float m = __shfl_sync(FULLMASK, alpha0, 0);

    // ---- depth-QD prefetch queue (clamped addresses) ----
    float pf0[QD], pf1[QD], em[QD], gt[QD];
    {
        int ptag = t0tag;
#pragma unroll
        for (int s = 0; s < QD; s++) {
            int tp = s + 1; tp = (tp < len) ? tp : (len - 1);
            const float* ft = fb + tp * stride;
            pf0[s] = ft[j0];
            pf1[s] = has1 ? ft[j1] : 0.0f;
            const int tg = __ldg(&tagb[tp]);
            em[s] = ft[tg];
            gt[s] = trans_sh[tg * K_DIM + ptag];
            ptag = tg;
        }
    }
    int ptag_pf = __ldg(&tagb[(QD < len) ? QD : (len - 1)]);

    int t = 1;
    const int nquads = (len - 1) >> 2;
    const int rem = (len - 1) & 3;

    for (int q = 0; q < nquads; q++) {
#pragma unroll
        for (int s = 0; s < QD; s++) {
            // -------- consume slot s (step t); m is lagged (previous step's alpha0[0]) --------
            const float a0 = __expf(alpha0 - m);
            const float a1 = __expf(alpha1 - m);

            float* buf = a_sh[warp][s & 1];
            buf[j0] = a0;
            if (has1) buf[j1] = a1;
            __syncwarp();

            float s0a = 0.f, s0b = 0.f, s0c = 0.f, s0d = 0.f;
            float s1a = 0.f, s1b = 0.f, s1c = 0.f, s1d = 0.f;
            const float4* av = (const float4*)buf;
#pragma unroll
            for (int k = 0; k < K_DIM / 4; k++) {
                const float4 a = av[k];
                const int i = k * 4;
                s0a = fmaf(a.x, E0[i + 0], s0a);
                s0b = fmaf(a.y, E0[i + 1], s0b);
                s0c = fmaf(a.z, E0[i + 2], s0c);
                s0d = fmaf(a.w, E0[i + 3], s0d);
                s1a = fmaf(a.x, E1[i + 0], s1a);
                s1b = fmaf(a.y, E1[i + 1], s1b);
                s1c = fmaf(a.z, E1[i + 2], s1c);
                s1d = fmaf(a.w, E1[i + 3], s1d);
            }
            alpha0 = pf0[s] + m + __logf((s0a + s0b) + (s0c + s0d));
            alpha1 = pf1[s] + m + __logf((s1a + s1b) + (s1c + s1d));
            gold += gt[s] + em[s];

            // refresh lagged reference for next step (shadow of refill latency)
            m = __shfl_sync(FULLMASK, alpha0, 0);

            // -------- refill slot s with step t+QD (clamped) --------
            int tp = t + QD; tp = (tp < len) ? tp : (len - 1);
            const float* ft = fb + tp * stride;
            pf0[s] = ft[j0];
            pf1[s] = has1 ? ft[j1] : 0.0f;
            const int tg = __ldg(&tagb[tp]);
            em[s] = ft[tg];
            gt[s] = trans_sh[tg * K_DIM + ptag_pf];
            ptag_pf = tg;
            t++;
        }
    }

    // -------- remainder (0..3 steps) --------
#pragma unroll
    for (int s = 0; s < 3; s++) {
        if (s < rem) {
            const float a0 = __expf(alpha0 - m);
            const float a1 = __expf(alpha1 - m);

            float* buf = a_sh[warp][s & 1];
            __syncwarp();
            buf[j0] = a0;
            if (has1) buf[j1] = a1;
            __syncwarp();

            float s0a = 0.f, s0b = 0.f, s0c = 0.f, s0d = 0.f;
            float s1a = 0.f, s1b = 0.f, s1c = 0.f, s1d = 0.f;
            const float4* av = (const float4*)buf;
#pragma unroll
            for (int k = 0; k < K_DIM / 4; k++) {
                const float4 a = av[k];
                const int i = k * 4;
                s0a = fmaf(a.x, E0[i + 0], s0a);
                s0b = fmaf(a.y, E0[i + 1], s0b);
                s0c = fmaf(a.z, E0[i + 2], s0c);
                s0d = fmaf(a.w, E0[i + 3], s0d);
                s1a = fmaf(a.x, E1[i + 0], s1a);
                s1b = fmaf(a.y, E1[i + 1], s1b);
                s1c = fmaf(a.z, E1[i + 2], s1c);
                s1d = fmaf(a.w, E1[i + 3], s1d);
            }
            alpha0 = pf0[s] + m + __logf((s0a + s0b) + (s0c + s0d));
            alpha1 = pf1[s] + m + __logf((s1a + s1b) + (s1c + s1d));
            gold += gt[s] + em[s];

            m = __shfl_sync(FULLMASK, alpha0, 0);
        }
    }

    // ---- log_z = lse_j(alpha_j + trans[STOP, j]) ----
    float v0 = alpha0 + trans_sh[STOP_TAG * K_DIM + j0];
    float v1 = has1 ? (alpha1 + trans_sh[STOP_TAG * K_DIM + j1]) : -INFINITY;
    float mv = fmaxf(v0, v1);
#pragma unroll
    for (int off = 16; off > 0; off >>= 1)
        mv = fmaxf(mv, __shfl_xor_sync(FULLMASK, mv, off));
    float se = __expf(v0 - mv) + (has1 ? __expf(v1 - mv) : 0.0f);
#pragma unroll
    for (int off = 16; off > 0; off >>= 1)
        se += __shfl_xor_sync(FULLMASK, se, off);
    const float log_z = mv + __logf(se);

    const int lastTag = __ldg(&tagb[len - 1]);
    const float total = log_z - (gold + trans_sh[STOP_TAG * K_DIM + lastTag]);

    if (lane == 0) atomicAdd(out, total);
}

extern "C" void kernel_launch(void* const* d_in, const int* in_sizes, int n_in,
                              void* d_out, int out_size) {
    const float* feats   = (const float*)d_in[0];
    const float* trans   = (const float*)d_in[1];
    const int*   tags    = (const int*)d_in[2];
    const int*   lengths = (const int*)d_in[3];
    float* out = (float*)d_out;

    crf_pre<<<1, B_DIM>>>(lengths, out);
    crf_fwd<<<NBLOCKS, THREADS>>>(feats, trans, tags, lengths, out);
}

// round 8
// speedup vs baseline: 2.3032x; 1.5320x over previous
#include <cuda_runtime.h>
#include <math.h>

#define T_DIM 512
#define B_DIM 1024
#define K_DIM 48
#define START_TAG 46
#define STOP_TAG 47
#define NEG_VAL -10000.0f
#define FULLMASK 0xffffffffu
#define QD 4

__device__ int g_order[B_DIM];

// ---------- pre-kernel: zero out, sort chains longest-first ----------
__global__ void crf_pre(const int* __restrict__ lengths, float* __restrict__ out) {
    __shared__ int cnt[T_DIM + 1];
    __shared__ int off[T_DIM + 1];
    const int tid = threadIdx.x;              // 1024 threads == B_DIM
    for (int i = tid; i <= T_DIM; i += B_DIM) cnt[i] = 0;
    __syncthreads();
    const int len = lengths[tid];
    atomicAdd(&cnt[len], 1);
    __syncthreads();
    if (tid == 0) {
        int run = 0;
        for (int l = T_DIM; l >= 1; l--) { off[l] = run; run += cnt[l]; }
        out[0] = 0.0f;
    }
    __syncthreads();
    const int pos = atomicAdd(&off[len], 1);  // descending-length order
    g_order[pos] = tid;
}

// ---------- main: one block per chain; warp0 = forward half, warp1 = backward half ----------
__global__ __launch_bounds__(64) void crf_fwd(
    const float* __restrict__ feats,      // (T, B, K)
    const float* __restrict__ trans,      // (K, K)  [next, prev]
    const int*   __restrict__ tags,       // (B, T)
    const int*   __restrict__ lengths,    // (B,)
    float* __restrict__ out)
{
    __shared__ float trans_sh[K_DIM * K_DIM];
    __shared__ __align__(16) float a_sh[2][2][K_DIM];
    __shared__ __align__(16) float bb[K_DIM];
    __shared__ float gold_b_sh;

    const int tid = threadIdx.x;
    const int warp = tid >> 5;
    const int lane = tid & 31;
    const int j0 = lane;
    const int j1 = lane + 32;
    const bool has1 = (lane < 16);

    for (int i = tid; i < K_DIM * K_DIM; i += 64) trans_sh[i] = trans[i];
    __syncthreads();

    const int b = g_order[blockIdx.x];
    const int len = lengths[b];               // in [1, T]
    const int tau = (len - 1) >> 1;           // fwd steps = tau; bwd steps = len-1-tau
    const int stride = B_DIM * K_DIM;
    const float* fb = feats + b * K_DIM;
    const int* tagb = tags + b * T_DIM;

    if (warp == 0) {
        // ================= FORWARD: alpha over t = 0..tau =================
        float E0[K_DIM], E1[K_DIM];
#pragma unroll
        for (int i = 0; i < K_DIM; i++) {
            E0[i] = __expf(trans_sh[j0 * K_DIM + i]);
            E1[i] = has1 ? __expf(trans_sh[j1 * K_DIM + i]) : 0.0f;
        }

        float alpha0 = fb[j0] + trans_sh[j0 * K_DIM + START_TAG];
        float alpha1 = has1 ? (fb[j1] + trans_sh[j1 * K_DIM + START_TAG]) : NEG_VAL;

        const int t0tag = __ldg(&tagb[0]);
        float gold = trans_sh[t0tag * K_DIM + START_TAG] + fb[t0tag];
        float m = __shfl_sync(FULLMASK, alpha0, 0);

        const int lenf = tau + 1;             // steps = lenf-1 = tau
        float pf0[QD], pf1[QD], em[QD], gt[QD];
        {
            int ptag = t0tag;
#pragma unroll
            for (int s = 0; s < QD; s++) {
                int tp = s + 1; tp = (tp < lenf) ? tp : (lenf - 1);
                const float* ft = fb + tp * stride;
                pf0[s] = ft[j0];
                pf1[s] = has1 ? ft[j1] : 0.0f;
                const int tg = __ldg(&tagb[tp]);
                em[s] = ft[tg];
                gt[s] = trans_sh[tg * K_DIM + ptag];
                ptag = tg;
            }
        }
        int ptag_pf = __ldg(&tagb[(QD < lenf) ? QD : (lenf - 1)]);

        int t = 1;
        const int nquads = (lenf - 1) >> 2;
        const int rem = (lenf - 1) & 3;

        for (int q = 0; q < nquads; q++) {
#pragma unroll
            for (int s = 0; s < QD; s++) {
                const float a0 = __expf(alpha0 - m);
                const float a1 = __expf(alpha1 - m);
                float* buf = a_sh[0][s & 1];
                buf[j0] = a0;
                if (has1) buf[j1] = a1;
                __syncwarp();

                float s0a = 0.f, s0b = 0.f, s0c = 0.f, s0d = 0.f;
                float s1a = 0.f, s1b = 0.f, s1c = 0.f, s1d = 0.f;
                const float4* av = (const float4*)buf;
#pragma unroll
                for (int k = 0; k < K_DIM / 4; k++) {
                    const float4 a = av[k];
                    const int i = k * 4;
                    s0a = fmaf(a.x, E0[i + 0], s0a);
                    s0b = fmaf(a.y, E0[i + 1], s0b);
                    s0c = fmaf(a.z, E0[i + 2], s0c);
                    s0d = fmaf(a.w, E0[i + 3], s0d);
                    s1a = fmaf(a.x, E1[i + 0], s1a);
                    s1b = fmaf(a.y, E1[i + 1], s1b);
                    s1c = fmaf(a.z, E1[i + 2], s1c);
                    s1d = fmaf(a.w, E1[i + 3], s1d);
                }
                alpha0 = pf0[s] + m + __logf((s0a + s0b) + (s0c + s0d));
                alpha1 = pf1[s] + m + __logf((s1a + s1b) + (s1c + s1d));
                gold += gt[s] + em[s];
                m = __shfl_sync(FULLMASK, alpha0, 0);

                int tp = t + QD; tp = (tp < lenf) ? tp : (lenf - 1);
                const float* ft = fb + tp * stride;
                pf0[s] = ft[j0];
                pf1[s] = has1 ? ft[j1] : 0.0f;
                const int tg = __ldg(&tagb[tp]);
                em[s] = ft[tg];
                gt[s] = trans_sh[tg * K_DIM + ptag_pf];
                ptag_pf = tg;
                t++;
            }
        }
#pragma unroll
        for (int s = 0; s < 3; s++) {
            if (s < rem) {
                const float a0 = __expf(alpha0 - m);
                const float a1 = __expf(alpha1 - m);
                float* buf = a_sh[0][s & 1];
                __syncwarp();
                buf[j0] = a0;
                if (has1) buf[j1] = a1;
                __syncwarp();

                float s0a = 0.f, s0b = 0.f, s0c = 0.f, s0d = 0.f;
                float s1a = 0.f, s1b = 0.f, s1c = 0.f, s1d = 0.f;
                const float4* av = (const float4*)buf;
#pragma unroll
                for (int k = 0; k < K_DIM / 4; k++) {
                    const float4 a = av[k];
                    const int i = k * 4;
                    s0a = fmaf(a.x, E0[i + 0], s0a);
                    s0b = fmaf(a.y, E0[i + 1], s0b);
                    s0c = fmaf(a.z, E0[i + 2], s0c);
                    s0d = fmaf(a.w, E0[i + 3], s0d);
                    s1a = fmaf(a.x, E1[i + 0], s1a);
                    s1b = fmaf(a.y, E1[i + 1], s1b);
                    s1c = fmaf(a.z, E1[i + 2], s1c);
                    s1d = fmaf(a.w, E1[i + 3], s1d);
                }
                alpha0 = pf0[s] + m + __logf((s0a + s0b) + (s0c + s0d));
                alpha1 = pf1[s] + m + __logf((s1a + s1b) + (s1c + s1d));
                gold += gt[s] + em[s];
                m = __shfl_sync(FULLMASK, alpha0, 0);
            }
        }

        // -------- combine with backward half --------
        __syncthreads();
        float v0 = alpha0 + bb[j0];
        float v1 = has1 ? (alpha1 + bb[j1]) : -INFINITY;
        float mv = fmaxf(v0, v1);
#pragma unroll
        for (int off = 16; off > 0; off >>= 1)
            mv = fmaxf(mv, __shfl_xor_sync(FULLMASK, mv, off));
        float se = __expf(v0 - mv) + (has1 ? __expf(v1 - mv) : 0.0f);
#pragma unroll
        for (int off = 16; off > 0; off >>= 1)
            se += __shfl_xor_sync(FULLMASK, se, off);
        const float log_z = mv + __logf(se);
        if (lane == 0) atomicAdd(out, log_z - (gold + gold_b_sh));

    } else {
        // ================= BACKWARD: beta over t = len-1 .. tau+1 =================
        // beta_{t-1}[i] = lse_j( trans[j,i] + feat_t[j] + beta_t[j] ),  beta_{len-1}[i] = trans[STOP,i]
        float ET0[K_DIM], ET1[K_DIM];
#pragma unroll
        for (int jj = 0; jj < K_DIM; jj++) {
            ET0[jj] = __expf(trans_sh[jj * K_DIM + j0]);
            ET1[jj] = has1 ? __expf(trans_sh[jj * K_DIM + j1]) : 0.0f;
        }

        float lb0 = trans_sh[STOP_TAG * K_DIM + j0];
        float lb1 = has1 ? trans_sh[STOP_TAG * K_DIM + j1] : NEG_VAL;
        float m = __shfl_sync(FULLMASK, lb0, 0);

        const int lastTag = __ldg(&tagb[len - 1]);
        float gold = trans_sh[STOP_TAG * K_DIM + lastTag];

        const int tlo = tau + 1;                  // lowest consumed time index
        const int count = len - 1 - tau;          // number of backward steps
        float pf0[QD], pf1[QD], em[QD], gt[QD];
#pragma unroll
        for (int s = 0; s < QD; s++) {
            int tp = len - 1 - s; if (tp < tlo) tp = tlo;   // always in [1, T-1]
            const float* ft = fb + tp * stride;
            pf0[s] = ft[j0];
            pf1[s] = has1 ? ft[j1] : 0.0f;
            const int tg = __ldg(&tagb[tp]);
            const int tgm = __ldg(&tagb[tp - 1]);
            em[s] = ft[tg];
            gt[s] = trans_sh[tg * K_DIM + tgm];
        }

        int t = len - 1;
        const int nquads = count >> 2;
        const int rem = count & 3;

        for (int q = 0; q < nquads; q++) {
#pragma unroll
            for (int s = 0; s < QD; s++) {
                const float a0 = __expf((pf0[s] + lb0) - m);
                const float a1 = __expf((pf1[s] + lb1) - m);
                float* buf = a_sh[1][s & 1];
                buf[j0] = a0;
                if (has1) buf[j1] = a1;
                __syncwarp();

                float s0a = 0.f, s0b = 0.f, s0c = 0.f, s0d = 0.f;
                float s1a = 0.f, s1b = 0.f, s1c = 0.f, s1d = 0.f;
                const float4* av = (const float4*)buf;
#pragma unroll
                for (int k = 0; k < K_DIM / 4; k++) {
                    const float4 a = av[k];
                    const int i = k * 4;
                    s0a = fmaf(a.x, ET0[i + 0], s0a);
                    s0b = fmaf(a.y, ET0[i + 1], s0b);
                    s0c = fmaf(a.z, ET0[i + 2], s0c);
                    s0d = fmaf(a.w, ET0[i + 3], s0d);
                    s1a = fmaf(a.x, ET1[i + 0], s1a);
                    s1b = fmaf(a.y, ET1[i + 1], s1b);
                    s1c = fmaf(a.z, ET1[i + 2], s1c);
                    s1d = fmaf(a.w, ET1[i + 3], s1d);
                }
                lb0 = m + __logf((s0a + s0b) + (s0c + s0d));
                lb1 = m + __logf((s1a + s1b) + (s1c + s1d));
                gold += gt[s] + em[s];
                m = __shfl_sync(FULLMASK, lb0, 0);

                int tp = t - QD; if (tp < tlo) tp = tlo;
                const float* ft = fb + tp * stride;
                pf0[s] = ft[j0];
                pf1[s] = has1 ? ft[j1] : 0.0f;
                const int tg = __ldg(&tagb[tp]);
                const int tgm = __ldg(&tagb[tp - 1]);
                em[s] = ft[tg];
                gt[s] = trans_sh[tg * K_DIM + tgm];
                t--;
            }
        }
#pragma unroll
        for (int s = 0; s < 3; s++) {
            if (s < rem) {
                const float a0 = __expf((pf0[s] + lb0) - m);
                const float a1 = __expf((pf1[s] + lb1) - m);
                float* buf = a_sh[1][s & 1];
                __syncwarp();
                buf[j0] = a0;
                if (has1) buf[j1] = a1;
                __syncwarp();

                float s0a = 0.f, s0b = 0.f, s0c = 0.f, s0d = 0.f;
                float s1a = 0.f, s1b = 0.f, s1c = 0.f, s1d = 0.f;
                const float4* av = (const float4*)buf;
#pragma unroll
                for (int k = 0; k < K_DIM / 4; k++) {
                    const float4 a = av[k];
                    const int i = k * 4;
                    s0a = fmaf(a.x, ET0[i + 0], s0a);
                    s0b = fmaf(a.y, ET0[i + 1], s0b);
                    s0c = fmaf(a.z, ET0[i + 2], s0c);
                    s0d = fmaf(a.w, ET0[i + 3], s0d);
                    s1a = fmaf(a.x, ET1[i + 0], s1a);
                    s1b = fmaf(a.y, ET1[i + 1], s1b);
                    s1c = fmaf(a.z, ET1[i + 2], s1c);
                    s1d = fmaf(a.w, ET1[i + 3], s1d);
                }
                lb0 = m + __logf((s0a + s0b) + (s0c + s0d));
                lb1 = m + __logf((s1a + s1b) + (s1c + s1d));
                gold += gt[s] + em[s];
                m = __shfl_sync(FULLMASK, lb0, 0);
            }
        }

        // -------- publish beta vector + gold_b --------
        bb[j0] = lb0;
        if (has1) bb[j1] = lb1;
        if (lane == 0) gold_b_sh = gold;
        __syncthreads();
    }
}

extern "C" void kernel_launch(void* const* d_in, const int* in_sizes, int n_in,
                              void* d_out, int out_size) {
    const float* feats   = (const float*)d_in[0];
    const float* trans   = (const float*)d_in[1];
    const int*   tags    = (const int*)d_in[2];
    const int*   lengths = (const int*)d_in[3];
    float* out = (float*)d_out;

    crf_pre<<<1, B_DIM>>>(lengths, out);
    crf_fwd<<<B_DIM, 64>>>(feats, trans, tags, lengths, out);
}

// round 9
// speedup vs baseline: 2.5054x; 1.0878x over previous
#include <cuda_runtime.h>
#include <math.h>

#define T_DIM 512
#define B_DIM 1024
#define K_DIM 48
#define START_TAG 46
#define STOP_TAG 47
#define NEG_VAL -10000.0f
#define FULLMASK 0xffffffffu
#define QD 4

typedef unsigned long long u64;

__device__ int g_order[B_DIM];

// ---------- packed f32x2 helpers ----------
__device__ __forceinline__ u64 pack2(float lo, float hi) {
    u64 r; asm("mov.b64 %0, {%1, %2};" : "=l"(r) : "f"(lo), "f"(hi)); return r;
}
__device__ __forceinline__ float2 unpack2f(u64 v) {
    float2 f; asm("mov.b64 {%0, %1}, %2;" : "=f"(f.x), "=f"(f.y) : "l"(v)); return f;
}
__device__ __forceinline__ u64 fma2(u64 a, u64 b, u64 c) {
    u64 d; asm("fma.rn.f32x2 %0, %1, %2, %3;" : "=l"(d) : "l"(a), "l"(b), "l"(c)); return d;
}
__device__ __forceinline__ u64 add2(u64 a, u64 b) {
    u64 d; asm("add.rn.f32x2 %0, %1, %2;" : "=l"(d) : "l"(a), "l"(b)); return d;
}

// matvec: s_j = sum_i E[j][i] * p_i, with E pre-packed along i (24 u64 per tag)
__device__ __forceinline__ void matvec2(const float* buf, const u64* Ea, const u64* Eb,
                                        float& s0, float& s1) {
    const double2* av = (const double2*)buf;
    u64 a0 = 0, a1 = 0, b0 = 0, b1 = 0;
#pragma unroll
    for (int k = 0; k < 12; k++) {
        const double2 d = av[k];
        const u64 plo = __double_as_longlong(d.x);   // (p_{4k},   p_{4k+1})
        const u64 phi = __double_as_longlong(d.y);   // (p_{4k+2}, p_{4k+3})
        a0 = fma2(plo, Ea[2 * k + 0], a0);
        a1 = fma2(phi, Ea[2 * k + 1], a1);
        b0 = fma2(plo, Eb[2 * k + 0], b0);
        b1 = fma2(phi, Eb[2 * k + 1], b1);
    }
    const float2 fa = unpack2f(add2(a0, a1));
    const float2 fb = unpack2f(add2(b0, b1));
    s0 = fa.x + fa.y;
    s1 = fb.x + fb.y;
}

// ---------- pre-kernel: zero out, sort chains longest-first ----------
__global__ void crf_pre(const int* __restrict__ lengths, float* __restrict__ out) {
    __shared__ int cnt[T_DIM + 1];
    __shared__ int off[T_DIM + 1];
    const int tid = threadIdx.x;              // 1024 threads == B_DIM
    for (int i = tid; i <= T_DIM; i += B_DIM) cnt[i] = 0;
    __syncthreads();
    const int len = lengths[tid];
    atomicAdd(&cnt[len], 1);
    __syncthreads();
    if (tid == 0) {
        int run = 0;
        for (int l = T_DIM; l >= 1; l--) { off[l] = run; run += cnt[l]; }
        out[0] = 0.0f;
    }
    __syncthreads();
    const int pos = atomicAdd(&off[len], 1);  // descending-length order
    g_order[pos] = tid;
}

// ---------- main: one block per chain; warp0 = forward half, warp1 = backward half ----------
__global__ __launch_bounds__(64) void crf_fwd(
    const float* __restrict__ feats,      // (T, B, K)
    const float* __restrict__ trans,      // (K, K)  [next, prev]
    const int*   __restrict__ tags,       // (B, T)
    const int*   __restrict__ lengths,    // (B,)
    float* __restrict__ out)
{
    __shared__ float trans_sh[K_DIM * K_DIM];
    __shared__ __align__(16) float a_sh[2][2][K_DIM];
    __shared__ __align__(16) float bb[K_DIM];
    __shared__ float gold_b_sh;

    const int tid = threadIdx.x;
    const int warp = tid >> 5;
    const int lane = tid & 31;
    const int j0 = lane;
    const int j1 = lane + 32;
    const bool has1 = (lane < 16);

    for (int i = tid; i < K_DIM * K_DIM; i += 64) trans_sh[i] = trans[i];
    __syncthreads();

    const int b = g_order[blockIdx.x];
    const int len = lengths[b];               // in [1, T]
    const int tau = (len - 1) >> 1;           // fwd steps = tau; bwd steps = len-1-tau
    const int stride = B_DIM * K_DIM;
    const float* fb = feats + b * K_DIM;
    const int* tagb = tags + b * T_DIM;

    if (warp == 0) {
        // ================= FORWARD: alpha over t = 0..tau =================
        // E rows packed along i: E0p[m] = (exp(tr[j0][2m]), exp(tr[j0][2m+1]))
        u64 E0p[K_DIM / 2], E1p[K_DIM / 2];
#pragma unroll
        for (int m2 = 0; m2 < K_DIM / 2; m2++) {
            E0p[m2] = pack2(__expf(trans_sh[j0 * K_DIM + 2 * m2]),
                            __expf(trans_sh[j0 * K_DIM + 2 * m2 + 1]));
            E1p[m2] = has1 ? pack2(__expf(trans_sh[j1 * K_DIM + 2 * m2]),
                                   __expf(trans_sh[j1 * K_DIM + 2 * m2 + 1]))
                           : 0ull;
        }

        float alpha0 = fb[j0] + trans_sh[j0 * K_DIM + START_TAG];
        float alpha1 = has1 ? (fb[j1] + trans_sh[j1 * K_DIM + START_TAG]) : NEG_VAL;

        const int t0tag = __ldg(&tagb[0]);
        float gold = trans_sh[t0tag * K_DIM + START_TAG] + fb[t0tag];
        float m = __shfl_sync(FULLMASK, alpha0, 0);

        const int lenf = tau + 1;             // steps = lenf-1 = tau
        float pf0[QD], pf1[QD], em[QD], gt[QD];
        {
            int ptag = t0tag;
#pragma unroll
            for (int s = 0; s < QD; s++) {
                int tp = s + 1; tp = (tp < lenf) ? tp : (lenf - 1);
                const float* ft = fb + tp * stride;
                pf0[s] = ft[j0];
                pf1[s] = has1 ? ft[j1] : 0.0f;
                const int tg = __ldg(&tagb[tp]);
                em[s] = ft[tg];
                gt[s] = trans_sh[tg * K_DIM + ptag];
                ptag = tg;
            }
        }
        int ptag_pf = __ldg(&tagb[(QD < lenf) ? QD : (lenf - 1)]);

        int t = 1;
        const int nquads = (lenf - 1) >> 2;
        const int rem = (lenf - 1) & 3;

        for (int q = 0; q < nquads; q++) {
#pragma unroll
            for (int s = 0; s < QD; s++) {
                const float a0 = __expf(alpha0 - m);
                const float a1 = __expf(alpha1 - m);
                float* buf = a_sh[0][s & 1];
                buf[j0] = a0;
                if (has1) buf[j1] = a1;
                __syncwarp();

                float s0, s1;
                matvec2(buf, E0p, E1p, s0, s1);
                alpha0 = pf0[s] + m + __logf(s0);
                alpha1 = pf1[s] + m + __logf(s1);
                gold += gt[s] + em[s];
                m = __shfl_sync(FULLMASK, alpha0, 0);

                int tp = t + QD; tp = (tp < lenf) ? tp : (lenf - 1);
                const float* ft = fb + tp * stride;
                pf0[s] = ft[j0];
                pf1[s] = has1 ? ft[j1] : 0.0f;
                const int tg = __ldg(&tagb[tp]);
                em[s] = ft[tg];
                gt[s] = trans_sh[tg * K_DIM + ptag_pf];
                ptag_pf = tg;
                t++;
            }
        }
#pragma unroll
        for (int s = 0; s < 3; s++) {
            if (s < rem) {
                const float a0 = __expf(alpha0 - m);
                const float a1 = __expf(alpha1 - m);
                float* buf = a_sh[0][s & 1];
                __syncwarp();
                buf[j0] = a0;
                if (has1) buf[j1] = a1;
                __syncwarp();

                float s0, s1;
                matvec2(buf, E0p, E1p, s0, s1);
                alpha0 = pf0[s] + m + __logf(s0);
                alpha1 = pf1[s] + m + __logf(s1);
                gold += gt[s] + em[s];
                m = __shfl_sync(FULLMASK, alpha0, 0);
            }
        }

        // -------- combine with backward half --------
        __syncthreads();
        float v0 = alpha0 + bb[j0];
        float v1 = has1 ? (alpha1 + bb[j1]) : -INFINITY;
        float mv = fmaxf(v0, v1);
#pragma unroll
        for (int off = 16; off > 0; off >>= 1)
            mv = fmaxf(mv, __shfl_xor_sync(FULLMASK, mv, off));
        float se = __expf(v0 - mv) + (has1 ? __expf(v1 - mv) : 0.0f);
#pragma unroll
        for (int off = 16; off > 0; off >>= 1)
            se += __shfl_xor_sync(FULLMASK, se, off);
        const float log_z = mv + __logf(se);
        if (lane == 0) atomicAdd(out, log_z - (gold + gold_b_sh));

    } else {
        // ================= BACKWARD: beta over t = len-1 .. tau+1 =================
        // beta_{t-1}[i] = lse_j( trans[j,i] + feat_t[j] + beta_t[j] );  ET[i][j] = trans[j][i]
        u64 ET0p[K_DIM / 2], ET1p[K_DIM / 2];
#pragma unroll
        for (int m2 = 0; m2 < K_DIM / 2; m2++) {
            ET0p[m2] = pack2(__expf(trans_sh[(2 * m2) * K_DIM + j0]),
                             __expf(trans_sh[(2 * m2 + 1) * K_DIM + j0]));
            ET1p[m2] = has1 ? pack2(__expf(trans_sh[(2 * m2) * K_DIM + j1]),
                                    __expf(trans_sh[(2 * m2 + 1) * K_DIM + j1]))
                            : 0ull;
        }

        float lb0 = trans_sh[STOP_TAG * K_DIM + j0];
        float lb1 = has1 ? trans_sh[STOP_TAG * K_DIM + j1] : NEG_VAL;
        float m = __shfl_sync(FULLMASK, lb0, 0);

        const int lastTag = __ldg(&tagb[len - 1]);
        float gold = trans_sh[STOP_TAG * K_DIM + lastTag];

        const int tlo = tau + 1;                  // lowest consumed time index
        const int count = len - 1 - tau;          // number of backward steps
        float pf0[QD], pf1[QD], em[QD], gt[QD];
#pragma unroll
        for (int s = 0; s < QD; s++) {
            int tp = len - 1 - s; if (tp < tlo) tp = tlo;   // always in [1, T-1]
            const float* ft = fb + tp * stride;
            pf0[s] = ft[j0];
            pf1[s] = has1 ? ft[j1] : 0.0f;
            const int tg = __ldg(&tagb[tp]);
            const int tgm = __ldg(&tagb[tp - 1]);
            em[s] = ft[tg];
            gt[s] = trans_sh[tg * K_DIM + tgm];
        }

        int t = len - 1;
        const int nquads = count >> 2;
        const int rem = count & 3;

        for (int q = 0; q < nquads; q++) {
#pragma unroll
            for (int s = 0; s < QD; s++) {
                const float a0 = __expf((pf0[s] + lb0) - m);
                const float a1 = __expf((pf1[s] + lb1) - m);
                float* buf = a_sh[1][s & 1];
                buf[j0] = a0;
                if (has1) buf[j1] = a1;
                __syncwarp();

                float s0, s1;
                matvec2(buf, ET0p, ET1p, s0, s1);
                lb0 = m + __logf(s0);
                lb1 = m + __logf(s1);
                gold += gt[s] + em[s];
                m = __shfl_sync(FULLMASK, lb0, 0);

                int tp = t - QD; if (tp < tlo) tp = tlo;
                const float* ft = fb + tp * stride;
                pf0[s] = ft[j0];
                pf1[s] = has1 ? ft[j1] : 0.0f;
                const int tg = __ldg(&tagb[tp]);
                const int tgm = __ldg(&tagb[tp - 1]);
                em[s] = ft[tg];
                gt[s] = trans_sh[tg * K_DIM + tgm];
                t--;
            }
        }
#pragma unroll
        for (int s = 0; s < 3; s++) {
            if (s < rem) {
                const float a0 = __expf((pf0[s] + lb0) - m);
                const float a1 = __expf((pf1[s] + lb1) - m);
                float* buf = a_sh[1][s & 1];
                __syncwarp();
                buf[j0] = a0;
                if (has1) buf[j1] = a1;
                __syncwarp();

                float s0, s1;
                matvec2(buf, ET0p, ET1p, s0, s1);
                lb0 = m + __logf(s0);
                lb1 = m + __logf(s1);
                gold += gt[s] + em[s];
                m = __shfl_sync(FULLMASK, lb0, 0);
            }
        }

        // -------- publish beta vector + gold_b --------
        bb[j0] = lb0;
        if (has1) bb[j1] = lb1;
        if (lane == 0) gold_b_sh = gold;
        __syncthreads();
    }
}

extern "C" void kernel_launch(void* const* d_in, const int* in_sizes, int n_in,
                              void* d_out, int out_size) {
    const float* feats   = (const float*)d_in[0];
    const float* trans   = (const float*)d_in[1];
    const int*   tags    = (const int*)d_in[2];
    const int*   lengths = (const int*)d_in[3];
    float* out = (float*)d_out;

    crf_pre<<<1, B_DIM>>>(lengths, out);
    crf_fwd<<<B_DIM, 64>>>(feats, trans, tags, lengths, out);
}

// round 12
// speedup vs baseline: 2.8134x; 1.1229x over previous
#include <cuda_runtime.h>
#include <math.h>

#define T_DIM 512
#define B_DIM 1024
#define K_DIM 48
#define START_TAG 46
#define STOP_TAG 47
#define NEG_VAL -10000.0f
#define FULLMASK 0xffffffffu
#define QD 4

typedef unsigned long long u64;

__device__ int g_order[B_DIM];

// ---------- packed f32x2 helpers ----------
__device__ __forceinline__ u64 pack2(float lo, float hi) {
    u64 r; asm("mov.b64 %0, {%1, %2};" : "=l"(r) : "f"(lo), "f"(hi)); return r;
}
__device__ __forceinline__ float2 unpack2f(u64 v) {
    float2 f; asm("mov.b64 {%0, %1}, %2;" : "=f"(f.x), "=f"(f.y) : "l"(v)); return f;
}
__device__ __forceinline__ u64 fma2(u64 a, u64 b, u64 c) {
    u64 d; asm("fma.rn.f32x2 %0, %1, %2, %3;" : "=l"(d) : "l"(a), "l"(b), "l"(c)); return d;
}
__device__ __forceinline__ u64 add2(u64 a, u64 b) {
    u64 d; asm("add.rn.f32x2 %0, %1, %2;" : "=l"(d) : "l"(a), "l"(b)); return d;
}

// matvec: s_j = sum_i E[j][i] * p_i, with E pre-packed along i (24 u64 per tag)
__device__ __forceinline__ void matvec2(const float* buf, const u64* Ea, const u64* Eb,
                                        float& s0, float& s1) {
    const double2* av = (const double2*)buf;
    u64 a0 = 0, a1 = 0, b0 = 0, b1 = 0;
#pragma unroll
    for (int k = 0; k < 12; k++) {
        const double2 d = av[k];
        const u64 plo = __double_as_longlong(d.x);   // (p_{4k},   p_{4k+1})
        const u64 phi = __double_as_longlong(d.y);   // (p_{4k+2}, p_{4k+3})
        a0 = fma2(plo, Ea[2 * k + 0], a0);
        a1 = fma2(phi, Ea[2 * k + 1], a1);
        b0 = fma2(plo, Eb[2 * k + 0], b0);
        b1 = fma2(phi, Eb[2 * k + 1], b1);
    }
    const float2 fa = unpack2f(add2(a0, a1));
    const float2 fb = unpack2f(add2(b0, b1));
    s0 = fa.x + fa.y;
    s1 = fb.x + fb.y;
}

// ---------- pre-kernel: zero out, sort chains longest-first ----------
__global__ void crf_pre(const int* __restrict__ lengths, float* __restrict__ out) {
    __shared__ int cnt[T_DIM + 1];
    __shared__ int off[T_DIM + 1];
    const int tid = threadIdx.x;              // 1024 threads == B_DIM
    for (int i = tid; i <= T_DIM; i += B_DIM) cnt[i] = 0;
    __syncthreads();
    const int len = lengths[tid];
    atomicAdd(&cnt[len], 1);
    __syncthreads();
    if (tid == 0) {
        int run = 0;
        for (int l = T_DIM; l >= 1; l--) { off[l] = run; run += cnt[l]; }
        out[0] = 0.0f;
    }
    __syncthreads();
    const int pos = atomicAdd(&off[len], 1);  // descending-length order
    g_order[pos] = tid;
}

// ---------- main: one block per chain; warp0 = forward half, warp1 = backward half ----------
__global__ __launch_bounds__(64) void crf_fwd(
    const float* __restrict__ feats,      // (T, B, K)
    const float* __restrict__ trans,      // (K, K)  [next, prev]
    const int*   __restrict__ tags,       // (B, T)
    const int*   __restrict__ lengths,    // (B,)
    float* __restrict__ out)
{
    __shared__ float trans_sh[K_DIM * K_DIM];
    __shared__ __align__(16) float a_sh[2][2][K_DIM];
    __shared__ __align__(16) float bb[K_DIM];
    __shared__ float gold_b_sh;

    const int tid = threadIdx.x;
    const int warp = tid >> 5;
    const int lane = tid & 31;
    const int j0 = lane;
    const int j1 = lane + 32;
    const bool has1 = (lane < 16);

    for (int i = tid; i < K_DIM * K_DIM; i += 64) trans_sh[i] = trans[i];
    __syncthreads();

    const int b = g_order[blockIdx.x];
    const int len = lengths[b];               // in [1, T]
    const int tau = (len - 1) >> 1;           // fwd steps = tau; bwd steps = len-1-tau
    const int stride = B_DIM * K_DIM;
    const float* fb = feats + b * K_DIM;
    const int* tagb = tags + b * T_DIM;

    if (warp == 0) {
        // ================= FORWARD (linear space): p over t = 0..tau =================
        u64 E0p[K_DIM / 2], E1p[K_DIM / 2];
#pragma unroll
        for (int m2 = 0; m2 < K_DIM / 2; m2++) {
            E0p[m2] = pack2(__expf(trans_sh[j0 * K_DIM + 2 * m2]),
                            __expf(trans_sh[j0 * K_DIM + 2 * m2 + 1]));
            E1p[m2] = has1 ? pack2(__expf(trans_sh[j1 * K_DIM + 2 * m2]),
                                   __expf(trans_sh[j1 * K_DIM + 2 * m2 + 1]))
                           : 0ull;
        }

        float p0 = __expf(fb[j0] + trans_sh[j0 * K_DIM + START_TAG]);
        float p1 = has1 ? __expf(fb[j1] + trans_sh[j1 * K_DIM + START_TAG]) : 0.0f;
        float Mlog = 0.0f;

        const int t0tag = __ldg(&tagb[0]);
        float gold = trans_sh[t0tag * K_DIM + START_TAG] + fb[t0tag];

        const int lenf = tau + 1;             // steps = lenf-1 = tau
        float ef0[QD], ef1[QD], em[QD], gt[QD];
        {
            int ptag = t0tag;
#pragma unroll
            for (int s = 0; s < QD; s++) {
                int tp = s + 1; tp = (tp < lenf) ? tp : (lenf - 1);
                const float* ft = fb + tp * stride;
                ef0[s] = __expf(ft[j0]);
                ef1[s] = has1 ? __expf(ft[j1]) : 0.0f;
                const int tg = __ldg(&tagb[tp]);
                em[s] = ft[tg];
                gt[s] = trans_sh[tg * K_DIM + ptag];
                ptag = tg;
            }
        }
        int ptag_pf = __ldg(&tagb[(QD < lenf) ? QD : (lenf - 1)]);

        int t = 1;
        const int nquads = (lenf - 1) >> 2;
        const int rem = (lenf - 1) & 3;

        for (int q = 0; q < nquads; q++) {
#pragma unroll
            for (int s = 0; s < QD; s++) {
                float* buf = a_sh[0][s & 1];
                buf[j0] = p0;
                if (has1) buf[j1] = p1;
                __syncwarp();

                float s0, s1;
                matvec2(buf, E0p, E1p, s0, s1);
                p0 = ef0[s] * s0;
                p1 = ef1[s] * s1;
                gold += gt[s] + em[s];

                int tp = t + QD; tp = (tp < lenf) ? tp : (lenf - 1);
                const float* ft = fb + tp * stride;
                ef0[s] = __expf(ft[j0]);
                ef1[s] = has1 ? __expf(ft[j1]) : 0.0f;
                const int tg = __ldg(&tagb[tp]);
                em[s] = ft[tg];
                gt[s] = trans_sh[tg * K_DIM + ptag_pf];
                ptag_pf = tg;
                t++;
            }
            // renorm every 4 steps (off the tight chain)
            const float x = __shfl_sync(FULLMASK, p0, 0);   // p[tag0] > 0 always
            Mlog += __logf(x);
            const float r = __frcp_rn(x);
            p0 *= r;
            p1 *= r;
        }
#pragma unroll
        for (int s = 0; s < 3; s++) {
            if (s < rem) {
                float* buf = a_sh[0][s & 1];
                __syncwarp();
                buf[j0] = p0;
                if (has1) buf[j1] = p1;
                __syncwarp();

                float s0, s1;
                matvec2(buf, E0p, E1p, s0, s1);
                p0 = ef0[s] * s0;
                p1 = ef1[s] * s1;
                gold += gt[s] + em[s];
            }
        }

        // convert to log once
        const float alpha0 = __logf(p0) + Mlog;
        const float alpha1 = has1 ? (__logf(p1) + Mlog) : -INFINITY;

        // -------- combine with backward half --------
        __syncthreads();
        float v0 = alpha0 + bb[j0];
        float v1 = has1 ? (alpha1 + bb[j1]) : -INFINITY;
        float mv = fmaxf(v0, v1);
#pragma unroll
        for (int off = 16; off > 0; off >>= 1)
            mv = fmaxf(mv, __shfl_xor_sync(FULLMASK, mv, off));
        float se = __expf(v0 - mv) + (has1 ? __expf(v1 - mv) : 0.0f);
#pragma unroll
        for (int off = 16; off > 0; off >>= 1)
            se += __shfl_xor_sync(FULLMASK, se, off);
        const float log_z = mv + __logf(se);
        if (lane == 0) atomicAdd(out, log_z - (gold + gold_b_sh));

    } else {
        // ================= BACKWARD (linear space): q over t = len-1 .. tau+1 =================
        // q_{t-1} = E^T * (ef_t ⊙ q_t);  q_{len-1}[i] = exp(trans[STOP,i])
        u64 ET0p[K_DIM / 2], ET1p[K_DIM / 2];
#pragma unroll
        for (int m2 = 0; m2 < K_DIM / 2; m2++) {
            ET0p[m2] = pack2(__expf(trans_sh[(2 * m2) * K_DIM + j0]),
                             __expf(trans_sh[(2 * m2 + 1) * K_DIM + j0]));
            ET1p[m2] = has1 ? pack2(__expf(trans_sh[(2 * m2) * K_DIM + j1]),
                                    __expf(trans_sh[(2 * m2 + 1) * K_DIM + j1]))
                            : 0ull;
        }

        float q0 = __expf(trans_sh[STOP_TAG * K_DIM + j0]);
        float q1 = has1 ? __expf(trans_sh[STOP_TAG * K_DIM + j1]) : 0.0f;
        float Nlog = 0.0f;

        const int lastTag = __ldg(&tagb[len - 1]);
        float gold = trans_sh[STOP_TAG * K_DIM + lastTag];

        const int tlo = tau + 1;                  // lowest consumed time index
        const int count = len - 1 - tau;          // number of backward steps
        float ef0[QD], ef1[QD], em[QD], gt[QD];
#pragma unroll
        for (int s = 0; s < QD; s++) {
            int tp = len - 1 - s; if (tp < tlo) tp = tlo;   // always in [1, T-1]
            const float* ft = fb + tp * stride;
            ef0[s] = __expf(ft[j0]);
            ef1[s] = has1 ? __expf(ft[j1]) : 0.0f;
            const int tg = __ldg(&tagb[tp]);
            const int tgm = __ldg(&tagb[tp - 1]);
            em[s] = ft[tg];
            gt[s] = trans_sh[tg * K_DIM + tgm];
        }

        int t = len - 1;
        const int nquads = count >> 2;
        const int rem = count & 3;

        for (int q = 0; q < nquads; q++) {
#pragma unroll
            for (int s = 0; s < QD; s++) {
                float* buf = a_sh[1][s & 1];
                buf[j0] = ef0[s] * q0;
                if (has1) buf[j1] = ef1[s] * q1;
                __syncwarp();

                float s0, s1;
                matvec2(buf, ET0p, ET1p, s0, s1);
                q0 = s0;
                q1 = s1;
                gold += gt[s] + em[s];

                int tp = t - QD; if (tp < tlo) tp = tlo;
                const float* ft = fb + tp * stride;
                ef0[s] = __expf(ft[j0]);
                ef1[s] = has1 ? __expf(ft[j1]) : 0.0f;
                const int tg = __ldg(&tagb[tp]);
                const int tgm = __ldg(&tagb[tp - 1]);
                em[s] = ft[tg];
                gt[s] = trans_sh[tg * K_DIM + tgm];
                t--;
            }
            // renorm every 4 steps
            const float x = __shfl_sync(FULLMASK, q0, 0);   // q[tag0] > 0 always
            Nlog += __logf(x);
            const float r = __frcp_rn(x);
            q0 *= r;
            q1 *= r;
        }
#pragma unroll
        for (int s = 0; s < 3; s++) {
            if (s < rem) {
                float* buf = a_sh[1][s & 1];
                __syncwarp();
                buf[j0] = ef0[s] * q0;
                if (has1) buf[j1] = ef1[s] * q1;
                __syncwarp();

                float s0, s1;
                matvec2(buf, ET0p, ET1p, s0, s1);
                q0 = s0;
                q1 = s1;
                gold += gt[s] + em[s];
            }
        }

        // -------- publish log-beta vector + gold_b --------
        bb[j0] = __logf(q0) + Nlog;
        if (has1) bb[j1] = __logf(q1) + Nlog;
        if (lane == 0) gold_b_sh = gold;
        __syncthreads();
    }
}

extern "C" void kernel_launch(void* const* d_in, const int* in_sizes, int n_in,
                              void* d_out, int out_size) {
    const float* feats   = (const float*)d_in[0];
    const float* trans   = (const float*)d_in[1];
    const int*   tags    = (const int*)d_in[2];
    const int*   lengths = (const int*)d_in[3];
    float* out = (float*)d_out;

    crf_pre<<<1, B_DIM>>>(lengths, out);
    crf_fwd<<<B_DIM, 64>>>(feats, trans, tags, lengths, out);
}